// round 4
// baseline (speedup 1.0000x reference)
#include <cuda_runtime.h>
#include <math.h>

#define NV 3
#define NA 4
#define NN 50000
#define NC 128

// Scratch (persistent __device__ globals; zeroed each launch via memsetAsync)
__device__ float g_s[NV * NA * NC];   // column sums of x over n
__device__ float g_u[NV * NA * NC];   // u[v,a,c] = sum_d (s[v,a,d]/N) * W[v,d,c]
__device__ float g_t[NV * NA];        // t[v,a]  = sum_d (s[v,a,d]/N) * b[v,d]

// -----------------------------------------------------------------------------
// Kernel 1: column sums over the node dimension.
// grid = (12, NCHUNKS), block = 256 (8 row-groups x 32 lanes, float4 per lane)
// -----------------------------------------------------------------------------
__global__ __launch_bounds__(256) void col_sum_kernel(const float* __restrict__ x) {
    const int va      = blockIdx.x;          // 0..11  (v*NA + a)
    const int nchunks = gridDim.y;
    const int rows    = (NN + nchunks - 1) / nchunks;
    const int n0      = blockIdx.y * rows;
    const int n1      = min(n0 + rows, NN);

    const int lane = threadIdx.x & 31;       // channel group (4 channels)
    const int w    = threadIdx.x >> 5;       // row group 0..7

    const float4* __restrict__ xb =
        reinterpret_cast<const float4*>(x) + (size_t)va * NN * (NC / 4);

    float4 acc = make_float4(0.f, 0.f, 0.f, 0.f);
    #pragma unroll 4
    for (int n = n0 + w; n < n1; n += 8) {
        float4 val = xb[(size_t)n * 32 + lane];
        acc.x += val.x; acc.y += val.y; acc.z += val.z; acc.w += val.w;
    }

    __shared__ float4 sm[256];
    sm[threadIdx.x] = acc;
    __syncthreads();

    if (threadIdx.x < 32) {
        float4 tot = sm[threadIdx.x];
        #pragma unroll
        for (int g = 1; g < 8; g++) {
            float4 val = sm[g * 32 + threadIdx.x];
            tot.x += val.x; tot.y += val.y; tot.z += val.z; tot.w += val.w;
        }
        float* dst = g_s + va * NC + threadIdx.x * 4;
        atomicAdd(dst + 0, tot.x);
        atomicAdd(dst + 1, tot.y);
        atomicAdd(dst + 2, tot.z);
        atomicAdd(dst + 3, tot.w);
    }
}

// -----------------------------------------------------------------------------
// Kernel 2 (tiny): u[v,a,:] = (s/N) @ W[v],  t[v,a] = (s/N) . b[v]
// grid = 12, block = 128
// -----------------------------------------------------------------------------
__global__ __launch_bounds__(128) void prep_kernel(const float* __restrict__ Wm,
                                                   const float* __restrict__ b) {
    const int va = blockIdx.x;
    const int v  = va / NA;
    const int c  = threadIdx.x;

    __shared__ float sh[NC];
    __shared__ float red[NC];

    sh[c] = g_s[va * NC + c] * (1.0f / (float)NN);
    __syncthreads();

    const float* __restrict__ Wv = Wm + (size_t)v * NC * NC;
    float acc = 0.f;
    #pragma unroll 8
    for (int d = 0; d < NC; d++) acc += sh[d] * Wv[d * NC + c];
    g_u[va * NC + c] = acc;

    red[c] = sh[c] * b[v * NC + c];
    __syncthreads();
    #pragma unroll
    for (int s2 = 64; s2 > 0; s2 >>= 1) {
        if (c < s2) red[c] += red[c + s2];
        __syncthreads();
    }
    if (c == 0) g_t[va] = red[0];
}

// -----------------------------------------------------------------------------
// Kernel 3: per node (a,n): scores -> tanh -> softmax over views -> combine.
// grid = (GX, NA), block = 256 (8 warps, one node per warp-iteration)
// -----------------------------------------------------------------------------
__global__ __launch_bounds__(256) void combine_kernel(const float* __restrict__ x,
                                                      float* __restrict__ out) {
    const int a    = blockIdx.y;
    const int lane = threadIdx.x & 31;
    const int warp = threadIdx.x >> 5;

    // Per-(a) constants: u slices (float4 per lane) and t scalars.
    const float4* ub = reinterpret_cast<const float4*>(g_u);
    const float4 u0 = ub[(size_t)(0 * NA + a) * 32 + lane];
    const float4 u1 = ub[(size_t)(1 * NA + a) * 32 + lane];
    const float4 u2 = ub[(size_t)(2 * NA + a) * 32 + lane];
    const float t0 = g_t[0 * NA + a];
    const float t1 = g_t[1 * NA + a];
    const float t2 = g_t[2 * NA + a];

    const size_t vstride = (size_t)NA * NN * 32;  // float4 units
    const float4* __restrict__ xb =
        reinterpret_cast<const float4*>(x) + (size_t)a * NN * 32;
    float4* __restrict__ ob =
        reinterpret_cast<float4*>(out) + (size_t)a * NN * 32;

    const int warps_in_grid = gridDim.x * 8;
    for (int n = blockIdx.x * 8 + warp; n < NN; n += warps_in_grid) {
        const size_t base = (size_t)n * 32 + lane;
        const float4 x0 = xb[base];
        const float4 x1 = xb[base + vstride];
        const float4 x2 = xb[base + 2 * vstride];

        float p0 = x0.x * u0.x + x0.y * u0.y + x0.z * u0.z + x0.w * u0.w;
        float p1 = x1.x * u1.x + x1.y * u1.y + x1.z * u1.z + x1.w * u1.w;
        float p2 = x2.x * u2.x + x2.y * u2.y + x2.z * u2.z + x2.w * u2.w;

        #pragma unroll
        for (int off = 16; off > 0; off >>= 1) {
            p0 += __shfl_xor_sync(0xFFFFFFFFu, p0, off);
            p1 += __shfl_xor_sync(0xFFFFFFFFu, p1, off);
            p2 += __shfl_xor_sync(0xFFFFFFFFu, p2, off);
        }

        const float e0 = __expf(tanhf(p0 + t0));
        const float e1 = __expf(tanhf(p1 + t1));
        const float e2 = __expf(tanhf(p2 + t2));
        const float inv = 1.0f / (e0 + e1 + e2);
        const float w0 = e0 * inv, w1 = e1 * inv, w2 = e2 * inv;

        float4 o;
        o.x = w0 * x0.x + w1 * x1.x + w2 * x2.x;
        o.y = w0 * x0.y + w1 * x1.y + w2 * x2.y;
        o.z = w0 * x0.z + w1 * x1.z + w2 * x2.z;
        o.w = w0 * x0.w + w1 * x1.w + w2 * x2.w;
        ob[base] = o;
    }
}

// -----------------------------------------------------------------------------
extern "C" void kernel_launch(void* const* d_in, const int* in_sizes, int n_in,
                              void* d_out, int out_size) {
    const float* x  = (const float*)d_in[0];   // [V,A,N,C]
    const float* Wm = (const float*)d_in[1];   // [V,C,C]
    const float* b  = (const float*)d_in[2];   // [V,C]
    float* out = (float*)d_out;                // [A,N,C]

    (void)in_sizes; (void)n_in; (void)out_size;

    void* d_s_ptr = nullptr;
    cudaGetSymbolAddress(&d_s_ptr, g_s);
    cudaMemsetAsync(d_s_ptr, 0, NV * NA * NC * sizeof(float));

    // Pass 1: column sums. 12 (v,a) pairs x 128 n-chunks = 1536 blocks.
    dim3 g1(NV * NA, 128);
    col_sum_kernel<<<g1, 256>>>(x);

    // Tiny prep: u and t.
    prep_kernel<<<NV * NA, 128>>>(Wm, b);

    // Pass 2: scores + softmax + combine. 625*8 warps * 10 iters = 50000 nodes.
    dim3 g3(625, NA);
    combine_kernel<<<g3, 256>>>(x, out);
}